// round 14
// baseline (speedup 1.0000x reference)
#include <cuda_runtime.h>
#include <math.h>

#define NEARV 0.01f
#define BLURV 0.3f
#define MAXA  0.999f
#define TQ    30.0f        // cull threshold: exp(-15)*op ~ 8e-8 max dropped alpha
#define MAXG  8192         // max C*N
#define NCHUNK 8
#define MAXPIX 131072      // max C*H*W
#define MAXTILE 4096       // max C * tilesX * tilesY
#define TILEX 32           // tile is 32x16 px; each thread owns 2 px (x and x+16)
#define TILEY 16
#define NB 592             // persistent blocks: 4 per SM on 148 SMs (all co-resident)

// record: f0=(m2x,m2y,A,B) f1=(C,lop,colR,colG) f2=(colB,bx,by,0)
// alpha = ex2( A*dx^2 + B*dx*dy + C*dy^2 + lop )
__device__ float  g_tz[MAXG];
__device__ float4 g_rec4[MAXG * 3];
__device__ float4 g_srec4[MAXG * 3];
__device__ float4 g_seg[NCHUNK * MAXPIX];   // per-chunk (r,g,b,T) per pixel
__device__ int    g_ctr[MAXTILE];           // combine tickets (self-reset per tile)
__device__ int    g_bar;                    // monotonic grid barrier (reset at exit)
__device__ int    g_work;                   // work-queue head (reset at exit)

__device__ __forceinline__ float ex2(float x) {
    float r; asm("ex2.approx.ftz.f32 %0, %1;" : "=f"(r) : "f"(x)); return r;
}

// Monotonic spin barrier with sleep backoff.
__device__ __forceinline__ void grid_barrier(int target) {
    __syncthreads();
    if (threadIdx.x == 0) {
        __threadfence();
        atomicAdd(&g_bar, 1);
        while (*((volatile int*)&g_bar) < target) __nanosleep(128);
        __threadfence();
    }
    __syncthreads();
}

// Center-out permutation: k=0 -> middle, then alternating outward (LPT order).
__device__ __forceinline__ int center_map(int k, int n) {
    int m = (n - 1) >> 1;
    int step = (k + 1) >> 1;
    return (k & 1) ? (m + step) : (m - step);
}

__global__ void __launch_bounds__(256, 4)
k_fused(const float* __restrict__ vms, const float* __restrict__ Ks,
        const float* __restrict__ means, const float* __restrict__ quats,
        const float* __restrict__ lscales, const float* __restrict__ olog,
        const float* __restrict__ clog, float* __restrict__ out,
        int C, int N, int W, int H, int tilesX, int tilesY) {
    __shared__ __align__(16) float4 sA[256];
    __shared__ __align__(16) float4 sB[256];
    __shared__ float sCb[256];
    __shared__ int s_off[9];
    __shared__ int s_misc;

    int tid = threadIdx.x;
    int lane = tid & 31, wid = tid >> 5;
    int gid = blockIdx.x * 256 + tid;

    // ================= Phase A: projection + conic + cull bbox ==============
    if (gid < C * N) {
        int cam = gid / N, i = gid - cam * N;
        const float* vm = vms + cam * 16;
        const float* K  = Ks  + cam * 9;
        float fx = K[0], fy = K[4], cx = K[2], cy = K[5];
        float W00 = vm[0], W01 = vm[1], W02 = vm[2],  t0 = vm[3];
        float W10 = vm[4], W11 = vm[5], W12 = vm[6],  t1 = vm[7];
        float W20 = vm[8], W21 = vm[9], W22 = vm[10], t2 = vm[11];

        float mx = means[i*3], my = means[i*3+1], mz = means[i*3+2];
        float tcx = W00*mx + W01*my + W02*mz + t0;
        float tcy = W10*mx + W11*my + W12*mz + t1;
        float tcz = W20*mx + W21*my + W22*mz + t2;

        float tzs = tcz > NEARV ? tcz : NEARV;
        float iz  = 1.0f / tzs;
        float m2x = fx * tcx * iz + cx;
        float m2y = fy * tcy * iz + cy;

        float4 qv = ((const float4*)quats)[i];
        float qw = qv.x, qx = qv.y, qy = qv.z, qz = qv.w;
        float qn = rsqrtf(qw*qw + qx*qx + qy*qy + qz*qz);
        qw *= qn; qx *= qn; qy *= qn; qz *= qn;
        float R00 = 1.f - 2.f*(qy*qy + qz*qz), R01 = 2.f*(qx*qy - qw*qz), R02 = 2.f*(qx*qz + qw*qy);
        float R10 = 2.f*(qx*qy + qw*qz), R11 = 1.f - 2.f*(qx*qx + qz*qz), R12 = 2.f*(qy*qz - qw*qx);
        float R20 = 2.f*(qx*qz - qw*qy), R21 = 2.f*(qy*qz + qw*qx), R22 = 1.f - 2.f*(qx*qx + qy*qy);

        float s0 = __expf(lscales[i*3]), s1 = __expf(lscales[i*3+1]), s2 = __expf(lscales[i*3+2]);

        float ja = fx * iz;
        float jc = -fx * tcx * iz * iz;
        float jb = fy * iz;
        float jd = -fy * tcy * iz * iz;

        float JW00 = ja*W00 + jc*W20, JW01 = ja*W01 + jc*W21, JW02 = ja*W02 + jc*W22;
        float JW10 = jb*W10 + jd*W20, JW11 = jb*W11 + jd*W21, JW12 = jb*W12 + jd*W22;

        float U00 = (JW00*R00 + JW01*R10 + JW02*R20) * s0;
        float U01 = (JW00*R01 + JW01*R11 + JW02*R21) * s1;
        float U02 = (JW00*R02 + JW01*R12 + JW02*R22) * s2;
        float U10 = (JW10*R00 + JW11*R10 + JW12*R20) * s0;
        float U11 = (JW10*R01 + JW11*R11 + JW12*R21) * s1;
        float U12 = (JW10*R02 + JW11*R12 + JW12*R22) * s2;

        float ca = U00*U00 + U01*U01 + U02*U02 + BLURV;
        float cc = U10*U10 + U11*U11 + U12*U12 + BLURV;
        float cb = U00*U10 + U01*U11 + U02*U12;

        float det = ca*cc - cb*cb;
        bool valid = (tcz > NEARV) && (det > 1e-12f);

        float op = 1.0f / (1.0f + __expf(-olog[i]));
        const float HL2E = 0.72134752044f;   // 0.5*log2(e)
        float A = 0.f, Bc = 0.f, Cc = 0.f, lop = -1e30f, bx = 0.f, by = 0.f;
        if (valid) {
            float idet = 1.0f / det;
            A  = -HL2E * (cc * idet);
            Bc = 2.0f * HL2E * (cb * idet);
            Cc = -HL2E * (ca * idet);
            lop = __log2f(op);
            bx = sqrtf(TQ * ca);
            by = sqrtf(TQ * cc);
        } else {
            m2x = -1e8f; m2y = -1e8f;        // bbox never overlaps -> culled
        }

        float colr = 1.0f / (1.0f + __expf(-clog[i*3]));
        float colg = 1.0f / (1.0f + __expf(-clog[i*3+1]));
        float colb = 1.0f / (1.0f + __expf(-clog[i*3+2]));

        g_tz[gid] = tcz;
        g_rec4[gid*3 + 0] = make_float4(m2x, m2y, A, Bc);
        g_rec4[gid*3 + 1] = make_float4(Cc, lop, colr, colg);
        g_rec4[gid*3 + 2] = make_float4(colb, bx, by, 0.f);
    }

    grid_barrier(NB);

    // ====== Phase B: stable rank-count sort, one WARP per gaussian ==========
    {
        int wg = blockIdx.x * 8 + wid;       // global warp id
        if (wg < C * N) {
            int cam = wg / N, i = wg - cam * N;
            const float* tz = g_tz + cam * N;
            float ti = tz[i];
            int rank = 0;
            for (int j = lane; j < N; j += 32) {
                float tj = tz[j];
                rank += (tj < ti) || (tj == ti && j < i);   // stable
            }
            #pragma unroll
            for (int d = 16; d > 0; d >>= 1)
                rank += __shfl_xor_sync(0xffffffffu, rank, d);
            if (lane < 3) {
                int src = (cam * N + i) * 3, dst = (cam * N + rank) * 3;
                g_srec4[dst + lane] = g_rec4[src + lane];
            }
        }
    }

    grid_barrier(2 * NB);

    // ===== Phase C: dynamic queue, 32x16 tiles, 2 px/thread (x and x+16) ====
    int total = tilesX * tilesY * C * NCHUNK;
    int L = (N + NCHUNK - 1) / NCHUNK;

    for (;;) {
        __syncthreads();                     // protect smem reuse across items
        if (tid == 0) s_misc = atomicAdd(&g_work, 1);
        __syncthreads();
        int item = s_misc;
        if (item >= total) break;

        int tmp = item;
        int chunk = tmp % NCHUNK; tmp /= NCHUNK;
        int cam   = tmp % C;      tmp /= C;
        int tx    = center_map(tmp % tilesX, tilesX);
        int ty    = center_map(tmp / tilesX, tilesY);

        int gs = chunk * L, ge = min(N, gs + L);
        int x0 = tx * TILEX + (tid & 15);
        int x1 = x0 + 16;
        int y  = ty * TILEY + (tid >> 4);
        bool in0 = (x0 < W) && (y < H);
        bool in1 = (x1 < W) && (y < H);
        float px0 = x0 + 0.5f, px1 = x1 + 0.5f, pyf = y + 0.5f;
        float tx0 = tx * TILEX + 0.5f, tx1v = tx0 + (TILEX - 1);
        float ty0 = ty * TILEY + 0.5f, ty1v = ty0 + (TILEY - 1);

        float T0 = in0 ? 1.0f : 0.0f, T1 = in1 ? 1.0f : 0.0f;
        float r0 = 0.f, g0 = 0.f, b0 = 0.f;
        float r1 = 0.f, g1 = 0.f, b1 = 0.f;
        int base = cam * N;

        for (int b0i = gs; b0i < ge; b0i += 256) {
            int gi = b0i + tid;
            bool keep = false;
            float4 f0, f2;
            if (gi < ge) {
                f0 = g_srec4[(base + gi) * 3];
                f2 = g_srec4[(base + gi) * 3 + 2];
                keep = (f0.x - f2.y <= tx1v) && (f0.x + f2.y >= tx0) &&
                       (f0.y - f2.z <= ty1v) && (f0.y + f2.z >= ty0);
            }
            unsigned m = __ballot_sync(0xffffffffu, keep);
            if (lane == 0) s_off[wid] = __popc(m);
            __syncthreads();
            if (wid == 0) {                 // warp-uniform 8-wide exclusive scan
                int v = (lane < 8) ? s_off[lane] : 0;
                int acc = v;
                #pragma unroll
                for (int d = 1; d < 8; d <<= 1) {
                    int n2 = __shfl_up_sync(0xffffffffu, acc, d);
                    if (lane >= d) acc += n2;
                }
                if (lane < 8) s_off[lane] = acc - v;
                if (lane == 7) s_off[8] = acc;
            }
            __syncthreads();
            if (keep) {
                float4 f1 = g_srec4[(base + gi) * 3 + 1];
                int pos = s_off[wid] + __popc(m & ((1u << lane) - 1));
                sA[pos] = f0; sB[pos] = f1;
                sCb[pos] = f2.x;
            }
            int cnt = s_off[8];
            __syncthreads();

            // branchless compositing, 2 px/thread; y-terms shared
            #pragma unroll 2
            for (int k = 0; k < cnt; k++) {
                float4 a = sA[k], b = sB[k];
                float cb2 = sCb[k];
                float dy = pyf - a.y;
                float s  = a.w * dy;                      // B*dy (shared)
                float t2 = fmaf(b.x * dy, dy, b.y);       // C*dy^2 + lop (shared)

                float dx0 = px0 - a.x;
                float e0 = fmaf(dx0, fmaf(a.z, dx0, s), t2);
                float al0 = fminf(ex2(e0), MAXA);
                float w0 = al0 * T0;
                r0 += w0 * b.z; g0 += w0 * b.w; b0 += w0 * cb2;
                T0 -= w0;

                float dx1 = px1 - a.x;
                float e1 = fmaf(dx1, fmaf(a.z, dx1, s), t2);
                float al1 = fminf(ex2(e1), MAXA);
                float w1 = al1 * T1;
                r1 += w1 * b.z; g1 += w1 * b.w; b1 += w1 * cb2;
                T1 -= w1;
            }
        }

        int pix0 = (cam * H + y) * W + x0;
        int pix1 = pix0 + 16;
        if (in0) g_seg[chunk * MAXPIX + pix0] = make_float4(r0, g0, b0, T0);
        if (in1) g_seg[chunk * MAXPIX + pix1] = make_float4(r1, g1, b1, T1);

        // ---- ticket: last chunk for this (cam,tile) combines all chunks ----
        __threadfence();
        int tix = (cam * tilesY + ty) * tilesX + tx;
        __syncthreads();
        if (tid == 0) s_misc = (atomicAdd(&g_ctr[tix], 1) == NCHUNK - 1);
        __syncthreads();

        if (s_misc) {
            if (in0) {
                float Tc = 1.f, r = 0.f, g = 0.f, b = 0.f;
                #pragma unroll
                for (int s2 = 0; s2 < NCHUNK; s2++) {
                    float4 v = g_seg[s2 * MAXPIX + pix0];
                    r += Tc * v.x; g += Tc * v.y; b += Tc * v.z;
                    Tc *= v.w;
                }
                out[pix0*3] = r; out[pix0*3+1] = g; out[pix0*3+2] = b;
            }
            if (in1) {
                float Tc = 1.f, r = 0.f, g = 0.f, b = 0.f;
                #pragma unroll
                for (int s2 = 0; s2 < NCHUNK; s2++) {
                    float4 v = g_seg[s2 * MAXPIX + pix1];
                    r += Tc * v.x; g += Tc * v.y; b += Tc * v.z;
                    Tc *= v.w;
                }
                out[pix1*3] = r; out[pix1*3+1] = g; out[pix1*3+2] = b;
            }
            __syncthreads();
            if (tid == 0) g_ctr[tix] = 0;     // reset ticket for next replay
        }
    }

    // ---- exit ticket: last block to drain the queue resets global state ----
    __syncthreads();
    if (tid == 0) {
        __threadfence();
        if (atomicAdd(&g_bar, 1) == 3 * NB - 1) {
            g_bar  = 0;
            g_work = 0;
            __threadfence();
        }
    }
}

// ---------------------------------------------------------------------------
extern "C" void kernel_launch(void* const* d_in, const int* in_sizes, int n_in,
                              void* d_out, int out_size) {
    const float* vms   = (const float*)d_in[0];  // (C,4,4)
    const float* Ks    = (const float*)d_in[1];  // (C,3,3)
    const float* means = (const float*)d_in[2];  // (N,3)
    const float* quats = (const float*)d_in[3];  // (N,4)
    const float* lsc   = (const float*)d_in[4];  // (N,3)
    const float* olog  = (const float*)d_in[5];  // (N,)
    const float* clog  = (const float*)d_in[6];  // (N,3)

    int C = in_sizes[0] / 16;
    int N = in_sizes[2] / 3;
    int HW = out_size / (3 * C);
    int W = (int)(sqrt((double)HW) + 0.5);
    int H = HW / W;
    int tilesX = (W + TILEX - 1) / TILEX;
    int tilesY = (H + TILEY - 1) / TILEY;

    k_fused<<<NB, 256>>>(vms, Ks, means, quats, lsc, olog, clog,
                         (float*)d_out, C, N, W, H, tilesX, tilesY);
}

// round 15
// speedup vs baseline: 1.0490x; 1.0490x over previous
#include <cuda_runtime.h>
#include <math.h>

#define NEARV 0.01f
#define BLURV 0.3f
#define MAXA  0.999f
#define TQ    30.0f        // cull threshold: exp(-15)*op ~ 8e-8 max dropped alpha
#define MAXG  8192         // max C*N
#define NCHUNK 8
#define MAXPIX 131072      // max C*H*W
#define MAXTILE 4096       // max C * tilesX * tilesY
#define TILEX 32           // 32x16 tile; thread owns px (x, x+16) packed in f32x2
#define TILEY 16
#define NB 592             // persistent blocks: 4 per SM on 148 SMs (all co-resident)

typedef unsigned long long ull;

// planes: f0=(m2x,m2y,A,B) f1=(C,lop,colR,colG) f2=(xlo,xhi,ylo,yhi) + cB plane
// alpha = ex2( A*dx^2 + B*dx*dy + C*dy^2 + lop ), lop pre-clamped to log2(MAXA)
__device__ float  g_tz[MAXG];
__device__ float4 g_rec4[MAXG * 3];
__device__ float  g_cb[MAXG];
__device__ float4 g_srec4[MAXG * 3];
__device__ float  g_cbs[MAXG];
__device__ float4 g_seg[NCHUNK * MAXPIX];   // per-chunk (r,g,b,T) per pixel
__device__ int    g_ctr[MAXTILE];           // combine tickets (self-reset per tile)
__device__ int    g_bar;                    // monotonic grid barrier (reset at exit)
__device__ int    g_work;                   // work-queue head (reset at exit)

__device__ __forceinline__ float ex2(float x) {
    float r; asm("ex2.approx.ftz.f32 %0, %1;" : "=f"(r) : "f"(x)); return r;
}
__device__ __forceinline__ ull pk(float lo, float hi) {
    ull d; asm("mov.b64 %0, {%1, %2};" : "=l"(d) : "f"(lo), "f"(hi)); return d;
}
__device__ __forceinline__ void upk(float& lo, float& hi, ull v) {
    asm("mov.b64 {%0, %1}, %2;" : "=f"(lo), "=f"(hi) : "l"(v));
}
__device__ __forceinline__ ull fma2(ull a, ull b, ull c) {
    ull d; asm("fma.rn.f32x2 %0, %1, %2, %3;" : "=l"(d) : "l"(a), "l"(b), "l"(c)); return d;
}
__device__ __forceinline__ ull add2(ull a, ull b) {
    ull d; asm("add.rn.f32x2 %0, %1, %2;" : "=l"(d) : "l"(a), "l"(b)); return d;
}
__device__ __forceinline__ ull mul2(ull a, ull b) {
    ull d; asm("mul.rn.f32x2 %0, %1, %2;" : "=l"(d) : "l"(a), "l"(b)); return d;
}

// Monotonic spin barrier with sleep backoff.
__device__ __forceinline__ void grid_barrier(int target) {
    __syncthreads();
    if (threadIdx.x == 0) {
        __threadfence();
        atomicAdd(&g_bar, 1);
        while (*((volatile int*)&g_bar) < target) __nanosleep(128);
        __threadfence();
    }
    __syncthreads();
}

// Center-out permutation: k=0 -> middle, then alternating outward (LPT order).
__device__ __forceinline__ int center_map(int k, int n) {
    int m = (n - 1) >> 1;
    int step = (k + 1) >> 1;
    return (k & 1) ? (m + step) : (m - step);
}

__global__ void __launch_bounds__(256, 4)
k_fused(const float* __restrict__ vms, const float* __restrict__ Ks,
        const float* __restrict__ means, const float* __restrict__ quats,
        const float* __restrict__ lscales, const float* __restrict__ olog,
        const float* __restrict__ clog, float* __restrict__ out,
        int C, int N, int W, int H, int tilesX, int tilesY) {
    // interleaved 64B records: [0]=(-m2x,-m2x,A,A) [1]=(cR,cR,cG,cG)
    //                          [2]=(cB,cB,B,C)     [3]=(m2y,lop,-,-)
    __shared__ __align__(16) float4 sG[256 * 4];
    __shared__ int s_off[9];
    __shared__ int s_misc;

    int tid = threadIdx.x;
    int lane = tid & 31, wid = tid >> 5;
    int gid = blockIdx.x * 256 + tid;

    // ================= Phase A: projection + conic + cull bounds ============
    if (gid < C * N) {
        int cam = gid / N, i = gid - cam * N;
        const float* vm = vms + cam * 16;
        const float* K  = Ks  + cam * 9;
        float fx = K[0], fy = K[4], cx = K[2], cy = K[5];
        float W00 = vm[0], W01 = vm[1], W02 = vm[2],  t0 = vm[3];
        float W10 = vm[4], W11 = vm[5], W12 = vm[6],  t1 = vm[7];
        float W20 = vm[8], W21 = vm[9], W22 = vm[10], t2 = vm[11];

        float mx = means[i*3], my = means[i*3+1], mz = means[i*3+2];
        float tcx = W00*mx + W01*my + W02*mz + t0;
        float tcy = W10*mx + W11*my + W12*mz + t1;
        float tcz = W20*mx + W21*my + W22*mz + t2;

        float tzs = tcz > NEARV ? tcz : NEARV;
        float iz  = 1.0f / tzs;
        float m2x = fx * tcx * iz + cx;
        float m2y = fy * tcy * iz + cy;

        float4 qv = ((const float4*)quats)[i];
        float qw = qv.x, qx = qv.y, qy = qv.z, qz = qv.w;
        float qn = rsqrtf(qw*qw + qx*qx + qy*qy + qz*qz);
        qw *= qn; qx *= qn; qy *= qn; qz *= qn;
        float R00 = 1.f - 2.f*(qy*qy + qz*qz), R01 = 2.f*(qx*qy - qw*qz), R02 = 2.f*(qx*qz + qw*qy);
        float R10 = 2.f*(qx*qy + qw*qz), R11 = 1.f - 2.f*(qx*qx + qz*qz), R12 = 2.f*(qy*qz - qw*qx);
        float R20 = 2.f*(qx*qz - qw*qy), R21 = 2.f*(qy*qz + qw*qx), R22 = 1.f - 2.f*(qx*qx + qy*qy);

        float s0 = __expf(lscales[i*3]), s1 = __expf(lscales[i*3+1]), s2 = __expf(lscales[i*3+2]);

        float ja = fx * iz;
        float jc = -fx * tcx * iz * iz;
        float jb = fy * iz;
        float jd = -fy * tcy * iz * iz;

        float JW00 = ja*W00 + jc*W20, JW01 = ja*W01 + jc*W21, JW02 = ja*W02 + jc*W22;
        float JW10 = jb*W10 + jd*W20, JW11 = jb*W11 + jd*W21, JW12 = jb*W12 + jd*W22;

        float U00 = (JW00*R00 + JW01*R10 + JW02*R20) * s0;
        float U01 = (JW00*R01 + JW01*R11 + JW02*R21) * s1;
        float U02 = (JW00*R02 + JW01*R12 + JW02*R22) * s2;
        float U10 = (JW10*R00 + JW11*R10 + JW12*R20) * s0;
        float U11 = (JW10*R01 + JW11*R11 + JW12*R21) * s1;
        float U12 = (JW10*R02 + JW11*R12 + JW12*R22) * s2;

        float ca = U00*U00 + U01*U01 + U02*U02 + BLURV;
        float cc = U10*U10 + U11*U11 + U12*U12 + BLURV;
        float cb = U00*U10 + U01*U11 + U02*U12;

        float det = ca*cc - cb*cb;
        bool valid = (tcz > NEARV) && (det > 1e-12f);

        float op = 1.0f / (1.0f + __expf(-olog[i]));
        const float HL2E = 0.72134752044f;   // 0.5*log2(e)
        float A = 0.f, Bc = 0.f, Cc = 0.f, lop = -1e30f;
        float xlo = 1e8f, xhi = -1e8f, ylo = 1e8f, yhi = -1e8f;
        if (valid) {
            float idet = 1.0f / det;
            A  = -HL2E * (cc * idet);
            Bc = 2.0f * HL2E * (cb * idet);
            Cc = -HL2E * (ca * idet);
            lop = __log2f(fminf(op, MAXA));  // clamp here: al<=op<=MAXA, fmin-free loop
            float bx = sqrtf(TQ * ca);
            float by = sqrtf(TQ * cc);
            xlo = m2x - bx; xhi = m2x + bx;
            ylo = m2y - by; yhi = m2y + by;
        }

        float colr = 1.0f / (1.0f + __expf(-clog[i*3]));
        float colg = 1.0f / (1.0f + __expf(-clog[i*3+1]));
        float colb = 1.0f / (1.0f + __expf(-clog[i*3+2]));

        g_tz[gid] = tcz;
        g_rec4[gid*3 + 0] = make_float4(m2x, m2y, A, Bc);
        g_rec4[gid*3 + 1] = make_float4(Cc, lop, colr, colg);
        g_rec4[gid*3 + 2] = make_float4(xlo, xhi, ylo, yhi);
        g_cb[gid] = colb;
    }

    grid_barrier(NB);

    // ====== Phase B: stable rank-count sort, one WARP per gaussian ==========
    {
        int wg = blockIdx.x * 8 + wid;       // global warp id
        if (wg < C * N) {
            int cam = wg / N, i = wg - cam * N;
            const float* tz = g_tz + cam * N;
            float ti = tz[i];
            int rank = 0;
            for (int j = lane; j < N; j += 32) {
                float tj = tz[j];
                rank += (tj < ti) || (tj == ti && j < i);   // stable
            }
            #pragma unroll
            for (int d = 16; d > 0; d >>= 1)
                rank += __shfl_xor_sync(0xffffffffu, rank, d);
            int src = cam * N + i, dst = cam * N + rank;
            if (lane < 3)       g_srec4[dst*3 + lane] = g_rec4[src*3 + lane];
            else if (lane == 3) g_cbs[dst] = g_cb[src];
        }
    }

    grid_barrier(2 * NB);

    // ===== Phase C: dynamic queue, 32x16 tiles, packed f32x2 (2 px/thread) ==
    int total = tilesX * tilesY * C * NCHUNK;
    int L = (N + NCHUNK - 1) / NCHUNK;
    const ull NEG1 = pk(-1.0f, -1.0f);

    for (;;) {
        __syncthreads();                     // protect smem reuse across items
        if (tid == 0) s_misc = atomicAdd(&g_work, 1);
        __syncthreads();
        int item = s_misc;
        if (item >= total) break;

        int tmp = item;
        int chunk = tmp % NCHUNK; tmp /= NCHUNK;
        int cam   = tmp % C;      tmp /= C;
        int tx    = center_map(tmp % tilesX, tilesX);
        int ty    = center_map(tmp / tilesX, tilesY);

        int gs = chunk * L, ge = min(N, gs + L);
        int x0 = tx * TILEX + (tid & 15);
        int x1 = x0 + 16;
        int y  = ty * TILEY + (tid >> 4);
        bool in0 = (x0 < W) && (y < H);
        bool in1 = (x1 < W) && (y < H);
        float pyf = y + 0.5f;
        ull pxp = pk(x0 + 0.5f, x1 + 0.5f);
        float tx0v = tx * TILEX + 0.5f, tx1v = tx0v + (TILEX - 1);
        float ty0v = ty * TILEY + 0.5f, ty1v = ty0v + (TILEY - 1);

        ull Tp = pk(in0 ? 1.0f : 0.0f, in1 ? 1.0f : 0.0f);
        ull accR = 0ull, accG = 0ull, accB = 0ull;
        int base = cam * N;

        for (int b0i = gs; b0i < ge; b0i += 256) {
            int gi = b0i + tid;
            bool keep = false;
            if (gi < ge) {
                float4 bb = g_srec4[(base + gi) * 3 + 2];
                keep = (bb.x <= tx1v) && (bb.y >= tx0v) &&
                       (bb.z <= ty1v) && (bb.w >= ty0v);
            }
            unsigned m = __ballot_sync(0xffffffffu, keep);
            if (lane == 0) s_off[wid] = __popc(m);
            __syncthreads();
            if (wid == 0) {                 // warp-uniform 8-wide exclusive scan
                int v = (lane < 8) ? s_off[lane] : 0;
                int acc = v;
                #pragma unroll
                for (int d = 1; d < 8; d <<= 1) {
                    int n2 = __shfl_up_sync(0xffffffffu, acc, d);
                    if (lane >= d) acc += n2;
                }
                if (lane < 8) s_off[lane] = acc - v;
                if (lane == 7) s_off[8] = acc;
            }
            __syncthreads();
            if (keep) {
                float4 f0 = g_srec4[(base + gi) * 3];
                float4 f1 = g_srec4[(base + gi) * 3 + 1];
                float cb2 = g_cbs[base + gi];
                int pos = s_off[wid] + __popc(m & ((1u << lane) - 1));
                sG[pos*4 + 0] = make_float4(-f0.x, -f0.x, f0.z, f0.z);  // -m2x, A
                sG[pos*4 + 1] = make_float4(f1.z, f1.z, f1.w, f1.w);    // cR, cG
                sG[pos*4 + 2] = make_float4(cb2, cb2, f0.w, f1.x);      // cB, B, C
                sG[pos*4 + 3] = make_float4(f0.y, f1.y, 0.f, 0.f);      // m2y, lop
            }
            int cnt = s_off[8];
            __syncthreads();

            // packed f32x2 front-to-back compositing (2 px/instruction)
            #pragma unroll 2
            for (int k = 0; k < cnt; k++) {
                float4 v0 = sG[4*k + 0];
                float4 v1 = sG[4*k + 1];
                float4 v2 = sG[4*k + 2];
                float4 v3 = sG[4*k + 3];
                float dy  = pyf - v3.x;
                float s   = v2.z * dy;                      // B*dy (shared)
                float t2s = fmaf(v2.w * dy, dy, v3.y);      // C*dy^2 + lop (shared)
                ull dxp = add2(pxp, pk(v0.x, v0.y));        // px + (-m2x)
                ull t1p = fma2(pk(v0.z, v0.w), dxp, pk(s, s));
                ull e2p = fma2(dxp, t1p, pk(t2s, t2s));
                float e20, e21; upk(e20, e21, e2p);
                ull alp = pk(ex2(e20), ex2(e21));           // al <= op <= MAXA
                ull wp  = mul2(alp, Tp);
                accR = fma2(wp, pk(v1.x, v1.y), accR);
                accG = fma2(wp, pk(v1.z, v1.w), accG);
                accB = fma2(wp, pk(v2.x, v2.y), accB);
                Tp   = fma2(wp, NEG1, Tp);                  // T -= w
            }
        }

        float r0, r1, g0, g1, b0, b1, T0, T1;
        upk(r0, r1, accR); upk(g0, g1, accG); upk(b0, b1, accB); upk(T0, T1, Tp);
        int pix0 = (cam * H + y) * W + x0;
        int pix1 = pix0 + 16;
        if (in0) g_seg[chunk * MAXPIX + pix0] = make_float4(r0, g0, b0, T0);
        if (in1) g_seg[chunk * MAXPIX + pix1] = make_float4(r1, g1, b1, T1);

        // ---- ticket: last chunk for this (cam,tile) combines all chunks ----
        __threadfence();
        int tix = (cam * tilesY + ty) * tilesX + tx;
        __syncthreads();
        if (tid == 0) s_misc = (atomicAdd(&g_ctr[tix], 1) == NCHUNK - 1);
        __syncthreads();

        if (s_misc) {
            if (in0) {
                float Tc = 1.f, r = 0.f, g = 0.f, b = 0.f;
                #pragma unroll
                for (int s2 = 0; s2 < NCHUNK; s2++) {
                    float4 v = g_seg[s2 * MAXPIX + pix0];
                    r += Tc * v.x; g += Tc * v.y; b += Tc * v.z;
                    Tc *= v.w;
                }
                out[pix0*3] = r; out[pix0*3+1] = g; out[pix0*3+2] = b;
            }
            if (in1) {
                float Tc = 1.f, r = 0.f, g = 0.f, b = 0.f;
                #pragma unroll
                for (int s2 = 0; s2 < NCHUNK; s2++) {
                    float4 v = g_seg[s2 * MAXPIX + pix1];
                    r += Tc * v.x; g += Tc * v.y; b += Tc * v.z;
                    Tc *= v.w;
                }
                out[pix1*3] = r; out[pix1*3+1] = g; out[pix1*3+2] = b;
            }
            __syncthreads();
            if (tid == 0) g_ctr[tix] = 0;     // reset ticket for next replay
        }
    }

    // ---- exit ticket: last block to drain the queue resets global state ----
    __syncthreads();
    if (tid == 0) {
        __threadfence();
        if (atomicAdd(&g_bar, 1) == 3 * NB - 1) {
            g_bar  = 0;
            g_work = 0;
            __threadfence();
        }
    }
}

// ---------------------------------------------------------------------------
extern "C" void kernel_launch(void* const* d_in, const int* in_sizes, int n_in,
                              void* d_out, int out_size) {
    const float* vms   = (const float*)d_in[0];  // (C,4,4)
    const float* Ks    = (const float*)d_in[1];  // (C,3,3)
    const float* means = (const float*)d_in[2];  // (N,3)
    const float* quats = (const float*)d_in[3];  // (N,4)
    const float* lsc   = (const float*)d_in[4];  // (N,3)
    const float* olog  = (const float*)d_in[5];  // (N,)
    const float* clog  = (const float*)d_in[6];  // (N,3)

    int C = in_sizes[0] / 16;
    int N = in_sizes[2] / 3;
    int HW = out_size / (3 * C);
    int W = (int)(sqrt((double)HW) + 0.5);
    int H = HW / W;
    int tilesX = (W + TILEX - 1) / TILEX;
    int tilesY = (H + TILEY - 1) / TILEY;

    k_fused<<<NB, 256>>>(vms, Ks, means, quats, lsc, olog, clog,
                         (float*)d_out, C, N, W, H, tilesX, tilesY);
}

// round 16
// speedup vs baseline: 1.1190x; 1.0667x over previous
#include <cuda_runtime.h>
#include <math.h>

#define NEARV 0.01f
#define BLURV 0.3f
#define MAXA  0.999f
#define TQ    30.0f        // cull threshold: exp(-15)*op ~ 8e-8 max dropped alpha
#define MAXG  8192         // max C*N
#define NCHUNK 8
#define MAXPIX 131072      // max C*H*W
#define MAXTILE 4096       // max C * tilesX * tilesY
#define TILE 16
#define NB 592             // persistent blocks: 4 per SM on 148 SMs (all co-resident)

// record: f0=(m2x,m2y,A,B) f1=(C,lop,colR,colG) f2=(colB,bx,by,0)
// alpha = ex2( A*dx^2 + B*dx*dy + C*dy^2 + lop ), lop pre-clamped to log2(MAXA)
__device__ float  g_tz[MAXG];
__device__ float4 g_rec4[MAXG * 3];
__device__ float4 g_srec4[MAXG * 3];
__device__ float4 g_seg[NCHUNK * MAXPIX];   // per-chunk (r,g,b,T) per pixel
__device__ int    g_ctr[MAXTILE];           // combine tickets (self-reset per tile)
__device__ int    g_bar;                    // monotonic grid barrier (reset at exit)
__device__ int    g_work;                   // work-queue head (reset at exit)

__device__ __forceinline__ float ex2(float x) {
    float r; asm("ex2.approx.ftz.f32 %0, %1;" : "=f"(r) : "f"(x)); return r;
}

// Monotonic spin barrier with sleep backoff.
__device__ __forceinline__ void grid_barrier(int target) {
    __syncthreads();
    if (threadIdx.x == 0) {
        __threadfence();
        atomicAdd(&g_bar, 1);
        while (*((volatile int*)&g_bar) < target) __nanosleep(128);
        __threadfence();
    }
    __syncthreads();
}

// Center-out permutation: k=0 -> middle, then alternating outward (LPT order).
__device__ __forceinline__ int center_map(int k, int n) {
    int m = (n - 1) >> 1;
    int step = (k + 1) >> 1;
    return (k & 1) ? (m + step) : (m - step);
}

__global__ void __launch_bounds__(256, 4)
k_fused(const float* __restrict__ vms, const float* __restrict__ Ks,
        const float* __restrict__ means, const float* __restrict__ quats,
        const float* __restrict__ lscales, const float* __restrict__ olog,
        const float* __restrict__ clog, float* __restrict__ out,
        int C, int N, int W, int H, int tilesX, int tilesY) {
    __shared__ __align__(16) float4 sA[256];
    __shared__ __align__(16) float4 sB[256];
    __shared__ float sCb[256];
    __shared__ int s_off[9];
    __shared__ int s_misc;

    int tid = threadIdx.x;
    int lane = tid & 31, wid = tid >> 5;
    int gid = blockIdx.x * 256 + tid;

    // ================= Phase A: projection + conic + cull bbox ==============
    if (gid < C * N) {
        int cam = gid / N, i = gid - cam * N;
        const float* vm = vms + cam * 16;
        const float* K  = Ks  + cam * 9;
        float fx = K[0], fy = K[4], cx = K[2], cy = K[5];
        float W00 = vm[0], W01 = vm[1], W02 = vm[2],  t0 = vm[3];
        float W10 = vm[4], W11 = vm[5], W12 = vm[6],  t1 = vm[7];
        float W20 = vm[8], W21 = vm[9], W22 = vm[10], t2 = vm[11];

        float mx = means[i*3], my = means[i*3+1], mz = means[i*3+2];
        float tcx = W00*mx + W01*my + W02*mz + t0;
        float tcy = W10*mx + W11*my + W12*mz + t1;
        float tcz = W20*mx + W21*my + W22*mz + t2;

        float tzs = tcz > NEARV ? tcz : NEARV;
        float iz  = 1.0f / tzs;
        float m2x = fx * tcx * iz + cx;
        float m2y = fy * tcy * iz + cy;

        float4 qv = ((const float4*)quats)[i];
        float qw = qv.x, qx = qv.y, qy = qv.z, qz = qv.w;
        float qn = rsqrtf(qw*qw + qx*qx + qy*qy + qz*qz);
        qw *= qn; qx *= qn; qy *= qn; qz *= qn;
        float R00 = 1.f - 2.f*(qy*qy + qz*qz), R01 = 2.f*(qx*qy - qw*qz), R02 = 2.f*(qx*qz + qw*qy);
        float R10 = 2.f*(qx*qy + qw*qz), R11 = 1.f - 2.f*(qx*qx + qz*qz), R12 = 2.f*(qy*qz - qw*qx);
        float R20 = 2.f*(qx*qz - qw*qy), R21 = 2.f*(qy*qz + qw*qx), R22 = 1.f - 2.f*(qx*qx + qy*qy);

        float s0 = __expf(lscales[i*3]), s1 = __expf(lscales[i*3+1]), s2 = __expf(lscales[i*3+2]);

        float ja = fx * iz;
        float jc = -fx * tcx * iz * iz;
        float jb = fy * iz;
        float jd = -fy * tcy * iz * iz;

        float JW00 = ja*W00 + jc*W20, JW01 = ja*W01 + jc*W21, JW02 = ja*W02 + jc*W22;
        float JW10 = jb*W10 + jd*W20, JW11 = jb*W11 + jd*W21, JW12 = jb*W12 + jd*W22;

        float U00 = (JW00*R00 + JW01*R10 + JW02*R20) * s0;
        float U01 = (JW00*R01 + JW01*R11 + JW02*R21) * s1;
        float U02 = (JW00*R02 + JW01*R12 + JW02*R22) * s2;
        float U10 = (JW10*R00 + JW11*R10 + JW12*R20) * s0;
        float U11 = (JW10*R01 + JW11*R11 + JW12*R21) * s1;
        float U12 = (JW10*R02 + JW11*R12 + JW12*R22) * s2;

        float ca = U00*U00 + U01*U01 + U02*U02 + BLURV;
        float cc = U10*U10 + U11*U11 + U12*U12 + BLURV;
        float cb = U00*U10 + U01*U11 + U02*U12;

        float det = ca*cc - cb*cb;
        bool valid = (tcz > NEARV) && (det > 1e-12f);

        float op = 1.0f / (1.0f + __expf(-olog[i]));
        const float HL2E = 0.72134752044f;   // 0.5*log2(e)
        float A = 0.f, Bc = 0.f, Cc = 0.f, lop = -1e30f, bx = 0.f, by = 0.f;
        if (valid) {
            float idet = 1.0f / det;
            A  = -HL2E * (cc * idet);
            Bc = 2.0f * HL2E * (cb * idet);
            Cc = -HL2E * (ca * idet);
            lop = __log2f(fminf(op, MAXA));  // pre-clamped: fmin-free hot loop
            bx = sqrtf(TQ * ca);
            by = sqrtf(TQ * cc);
        } else {
            m2x = -1e8f; m2y = -1e8f;        // bbox never overlaps -> culled
        }

        float colr = 1.0f / (1.0f + __expf(-clog[i*3]));
        float colg = 1.0f / (1.0f + __expf(-clog[i*3+1]));
        float colb = 1.0f / (1.0f + __expf(-clog[i*3+2]));

        g_tz[gid] = tcz;
        g_rec4[gid*3 + 0] = make_float4(m2x, m2y, A, Bc);
        g_rec4[gid*3 + 1] = make_float4(Cc, lop, colr, colg);
        g_rec4[gid*3 + 2] = make_float4(colb, bx, by, 0.f);
    }

    grid_barrier(NB);

    // ====== Phase B: stable rank-count sort, one WARP per gaussian ==========
    {
        int wg = blockIdx.x * 8 + wid;       // global warp id
        if (wg < C * N) {
            int cam = wg / N, i = wg - cam * N;
            const float* tz = g_tz + cam * N;
            float ti = tz[i];
            int rank = 0;
            for (int j = lane; j < N; j += 32) {
                float tj = tz[j];
                rank += (tj < ti) || (tj == ti && j < i);   // stable
            }
            #pragma unroll
            for (int d = 16; d > 0; d >>= 1)
                rank += __shfl_xor_sync(0xffffffffu, rank, d);
            if (lane < 3) {
                int src = (cam * N + i) * 3, dst = (cam * N + rank) * 3;
                g_srec4[dst + lane] = g_rec4[src + lane];
            }
        }
    }

    grid_barrier(2 * NB);

    // ================= Phase C: dynamic-queue tiled compositing =============
    // LPT order: heavy center tiles pulled first, light edge tiles pad tail.
    int total = tilesX * tilesY * C * NCHUNK;
    int L = (N + NCHUNK - 1) / NCHUNK;

    for (;;) {
        __syncthreads();                     // protect smem reuse across items
        if (tid == 0) s_misc = atomicAdd(&g_work, 1);
        __syncthreads();
        int item = s_misc;
        if (item >= total) break;

        int tmp = item;
        int chunk = tmp % NCHUNK; tmp /= NCHUNK;
        int cam   = tmp % C;      tmp /= C;
        int tx    = center_map(tmp % tilesX, tilesX);
        int ty    = center_map(tmp / tilesX, tilesY);

        int gs = chunk * L, ge = min(N, gs + L);
        int x = tx * TILE + (tid & 15);
        int y = ty * TILE + (tid >> 4);
        bool inside = (x < W) && (y < H);
        float pxf = x + 0.5f, pyf = y + 0.5f;
        float tx0 = tx * TILE + 0.5f, tx1 = tx0 + (TILE - 1);
        float ty0 = ty * TILE + 0.5f, ty1 = ty0 + (TILE - 1);

        float T = inside ? 1.0f : 0.0f;
        float aR = 0.f, aG = 0.f, aB = 0.f;
        int base = cam * N;

        for (int b0 = gs; b0 < ge; b0 += 256) {
            int gi = b0 + tid;
            bool keep = false;
            float4 f0, f2;
            if (gi < ge) {
                f0 = g_srec4[(base + gi) * 3];
                f2 = g_srec4[(base + gi) * 3 + 2];
                keep = (f0.x - f2.y <= tx1) && (f0.x + f2.y >= tx0) &&
                       (f0.y - f2.z <= ty1) && (f0.y + f2.z >= ty0);
            }
            unsigned m = __ballot_sync(0xffffffffu, keep);
            if (lane == 0) s_off[wid] = __popc(m);
            __syncthreads();
            if (wid == 0) {                 // warp-uniform 8-wide exclusive scan
                int v = (lane < 8) ? s_off[lane] : 0;
                int acc = v;
                #pragma unroll
                for (int d = 1; d < 8; d <<= 1) {
                    int n2 = __shfl_up_sync(0xffffffffu, acc, d);
                    if (lane >= d) acc += n2;
                }
                if (lane < 8) s_off[lane] = acc - v;
                if (lane == 7) s_off[8] = acc;
            }
            __syncthreads();
            if (keep) {
                float4 f1 = g_srec4[(base + gi) * 3 + 1];
                int pos = s_off[wid] + __popc(m & ((1u << lane) - 1));
                sA[pos] = f0; sB[pos] = f1;
                sCb[pos] = f2.x;
            }
            int cnt = s_off[8];
            __syncthreads();

            // compositing in 64-iter sub-loops; ONE collective saturation
            // check between sub-loops (uniform result -> clean break, inner
            // loops stay branch-free and unrolled)
            for (int k0 = 0; k0 < cnt; k0 += 64) {
                int ke = min(cnt, k0 + 64);
                #pragma unroll 2
                for (int k = k0; k < ke; k++) {
                    float4 a = sA[k], b = sB[k];
                    float cb2 = sCb[k];
                    float dx = pxf - a.x, dy = pyf - a.y;
                    float t1 = fmaf(a.w, dy, a.z * dx);       // A dx + B dy
                    float t2 = fmaf(b.x * dy, dy, b.y);       // C dy^2 + lop
                    float e2 = fmaf(dx, t1, t2);
                    float al = ex2(e2);                       // al <= op <= MAXA
                    float w  = al * T;
                    aR += w * b.z; aG += w * b.w; aB += w * cb2;
                    T -= w;
                }
                if (ke < cnt && __syncthreads_and(T < 1e-5f)) break;
            }
        }

        int pix = (cam * H + y) * W + x;
        if (inside)
            g_seg[chunk * MAXPIX + pix] = make_float4(aR, aG, aB, T);

        // ---- ticket: last chunk for this (cam,tile) combines all chunks ----
        __threadfence();
        int tix = (cam * tilesY + ty) * tilesX + tx;
        __syncthreads();
        if (tid == 0) s_misc = (atomicAdd(&g_ctr[tix], 1) == NCHUNK - 1);
        __syncthreads();

        if (s_misc) {
            if (inside) {
                float Tc = 1.f, r = 0.f, g = 0.f, b = 0.f;
                #pragma unroll
                for (int s = 0; s < NCHUNK; s++) {
                    float4 v = g_seg[s * MAXPIX + pix];
                    r += Tc * v.x; g += Tc * v.y; b += Tc * v.z;
                    Tc *= v.w;
                }
                out[pix*3] = r; out[pix*3+1] = g; out[pix*3+2] = b;
            }
            __syncthreads();
            if (tid == 0) g_ctr[tix] = 0;     // reset ticket for next replay
        }
    }

    // ---- exit ticket: last block to drain the queue resets global state ----
    __syncthreads();
    if (tid == 0) {
        __threadfence();
        if (atomicAdd(&g_bar, 1) == 3 * NB - 1) {
            g_bar  = 0;
            g_work = 0;
            __threadfence();
        }
    }
}

// ---------------------------------------------------------------------------
extern "C" void kernel_launch(void* const* d_in, const int* in_sizes, int n_in,
                              void* d_out, int out_size) {
    const float* vms   = (const float*)d_in[0];  // (C,4,4)
    const float* Ks    = (const float*)d_in[1];  // (C,3,3)
    const float* means = (const float*)d_in[2];  // (N,3)
    const float* quats = (const float*)d_in[3];  // (N,4)
    const float* lsc   = (const float*)d_in[4];  // (N,3)
    const float* olog  = (const float*)d_in[5];  // (N,)
    const float* clog  = (const float*)d_in[6];  // (N,3)

    int C = in_sizes[0] / 16;
    int N = in_sizes[2] / 3;
    int HW = out_size / (3 * C);
    int W = (int)(sqrt((double)HW) + 0.5);
    int H = HW / W;
    int tilesX = (W + TILE - 1) / TILE;
    int tilesY = (H + TILE - 1) / TILE;

    k_fused<<<NB, 256>>>(vms, Ks, means, quats, lsc, olog, clog,
                         (float*)d_out, C, N, W, H, tilesX, tilesY);
}

// round 17
// speedup vs baseline: 1.2149x; 1.0857x over previous
#include <cuda_runtime.h>
#include <math.h>

#define NEARV 0.01f
#define BLURV 0.3f
#define MAXA  0.999f
#define TQ    30.0f        // cull threshold: exp(-15)*op ~ 8e-8 max dropped alpha
#define MAXG  8192         // max C*N
#define NCHUNK 8
#define MAXPIX 131072      // max C*H*W
#define MAXTILE 4096       // max C * tilesX * tilesY
#define TILE 16
#define NB 592             // persistent blocks: 4 per SM on 148 SMs (all co-resident)

// record: f0=(m2x,m2y,A,B) f1=(C,lop,colR,colG) f2=(colB,bx,by,0)
// alpha = ex2( A*dx^2 + B*dx*dy + C*dy^2 + lop ), lop pre-clamped to log2(MAXA)
__device__ float  g_tz[MAXG];
__device__ float4 g_rec4[MAXG * 3];
__device__ float4 g_srec4[MAXG * 3];
__device__ float4 g_seg[NCHUNK * MAXPIX];   // per-chunk (r,g,b,T) per pixel
__device__ int    g_ctr[MAXTILE];           // combine tickets (self-reset per tile)
__device__ int    g_bar;                    // monotonic grid barrier (reset at exit)
__device__ int    g_work;                   // work-queue head (reset at exit)

__device__ __forceinline__ float ex2(float x) {
    float r; asm("ex2.approx.ftz.f32 %0, %1;" : "=f"(r) : "f"(x)); return r;
}

// Release+acquire ticket: orders this block's prior gmem writes (release) and
// makes other blocks' writes visible when we observe their arrivals (acquire).
// Replaces __threadfence() + relaxed atomicAdd.
__device__ __forceinline__ int atom_add_acqrel(int* p, int v) {
    int r;
    asm volatile("atom.add.acq_rel.gpu.global.s32 %0, [%1], %2;"
                 : "=r"(r) : "l"(p), "r"(v) : "memory");
    return r;
}

// Monotonic spin barrier with sleep backoff.
__device__ __forceinline__ void grid_barrier(int target) {
    __syncthreads();
    if (threadIdx.x == 0) {
        __threadfence();
        atomicAdd(&g_bar, 1);
        while (*((volatile int*)&g_bar) < target) __nanosleep(128);
        __threadfence();
    }
    __syncthreads();
}

// Center-out permutation: k=0 -> middle, then alternating outward (LPT order).
__device__ __forceinline__ int center_map(int k, int n) {
    int m = (n - 1) >> 1;
    int step = (k + 1) >> 1;
    return (k & 1) ? (m + step) : (m - step);
}

__global__ void __launch_bounds__(256, 4)
k_fused(const float* __restrict__ vms, const float* __restrict__ Ks,
        const float* __restrict__ means, const float* __restrict__ quats,
        const float* __restrict__ lscales, const float* __restrict__ olog,
        const float* __restrict__ clog, float* __restrict__ out,
        int C, int N, int W, int H, int tilesX, int tilesY) {
    __shared__ __align__(16) float4 sA[256];
    __shared__ __align__(16) float4 sB[256];
    __shared__ float sCb[256];
    __shared__ int s_off[8];
    __shared__ int s_item;
    __shared__ int s_last;

    int tid = threadIdx.x;
    int lane = tid & 31, wid = tid >> 5;
    int gid = blockIdx.x * 256 + tid;

    // ================= Phase A: projection + conic + cull bbox ==============
    if (gid < C * N) {
        int cam = gid / N, i = gid - cam * N;
        const float* vm = vms + cam * 16;
        const float* K  = Ks  + cam * 9;
        float fx = K[0], fy = K[4], cx = K[2], cy = K[5];
        float W00 = vm[0], W01 = vm[1], W02 = vm[2],  t0 = vm[3];
        float W10 = vm[4], W11 = vm[5], W12 = vm[6],  t1 = vm[7];
        float W20 = vm[8], W21 = vm[9], W22 = vm[10], t2 = vm[11];

        float mx = means[i*3], my = means[i*3+1], mz = means[i*3+2];
        float tcx = W00*mx + W01*my + W02*mz + t0;
        float tcy = W10*mx + W11*my + W12*mz + t1;
        float tcz = W20*mx + W21*my + W22*mz + t2;

        float tzs = tcz > NEARV ? tcz : NEARV;
        float iz  = 1.0f / tzs;
        float m2x = fx * tcx * iz + cx;
        float m2y = fy * tcy * iz + cy;

        float4 qv = ((const float4*)quats)[i];
        float qw = qv.x, qx = qv.y, qy = qv.z, qz = qv.w;
        float qn = rsqrtf(qw*qw + qx*qx + qy*qy + qz*qz);
        qw *= qn; qx *= qn; qy *= qn; qz *= qn;
        float R00 = 1.f - 2.f*(qy*qy + qz*qz), R01 = 2.f*(qx*qy - qw*qz), R02 = 2.f*(qx*qz + qw*qy);
        float R10 = 2.f*(qx*qy + qw*qz), R11 = 1.f - 2.f*(qx*qx + qz*qz), R12 = 2.f*(qy*qz - qw*qx);
        float R20 = 2.f*(qx*qz - qw*qy), R21 = 2.f*(qy*qz + qw*qx), R22 = 1.f - 2.f*(qx*qx + qy*qy);

        float s0 = __expf(lscales[i*3]), s1 = __expf(lscales[i*3+1]), s2 = __expf(lscales[i*3+2]);

        float ja = fx * iz;
        float jc = -fx * tcx * iz * iz;
        float jb = fy * iz;
        float jd = -fy * tcy * iz * iz;

        float JW00 = ja*W00 + jc*W20, JW01 = ja*W01 + jc*W21, JW02 = ja*W02 + jc*W22;
        float JW10 = jb*W10 + jd*W20, JW11 = jb*W11 + jd*W21, JW12 = jb*W12 + jd*W22;

        float U00 = (JW00*R00 + JW01*R10 + JW02*R20) * s0;
        float U01 = (JW00*R01 + JW01*R11 + JW02*R21) * s1;
        float U02 = (JW00*R02 + JW01*R12 + JW02*R22) * s2;
        float U10 = (JW10*R00 + JW11*R10 + JW12*R20) * s0;
        float U11 = (JW10*R01 + JW11*R11 + JW12*R21) * s1;
        float U12 = (JW10*R02 + JW11*R12 + JW12*R22) * s2;

        float ca = U00*U00 + U01*U01 + U02*U02 + BLURV;
        float cc = U10*U10 + U11*U11 + U12*U12 + BLURV;
        float cb = U00*U10 + U01*U11 + U02*U12;

        float det = ca*cc - cb*cb;
        bool valid = (tcz > NEARV) && (det > 1e-12f);

        float op = 1.0f / (1.0f + __expf(-olog[i]));
        const float HL2E = 0.72134752044f;   // 0.5*log2(e)
        float A = 0.f, Bc = 0.f, Cc = 0.f, lop = -1e30f, bx = 0.f, by = 0.f;
        if (valid) {
            float idet = 1.0f / det;
            A  = -HL2E * (cc * idet);
            Bc = 2.0f * HL2E * (cb * idet);
            Cc = -HL2E * (ca * idet);
            lop = __log2f(fminf(op, MAXA));  // pre-clamped: fmin-free hot loop
            bx = sqrtf(TQ * ca);
            by = sqrtf(TQ * cc);
        } else {
            m2x = -1e8f; m2y = -1e8f;        // bbox never overlaps -> culled
        }

        float colr = 1.0f / (1.0f + __expf(-clog[i*3]));
        float colg = 1.0f / (1.0f + __expf(-clog[i*3+1]));
        float colb = 1.0f / (1.0f + __expf(-clog[i*3+2]));

        g_tz[gid] = tcz;
        g_rec4[gid*3 + 0] = make_float4(m2x, m2y, A, Bc);
        g_rec4[gid*3 + 1] = make_float4(Cc, lop, colr, colg);
        g_rec4[gid*3 + 2] = make_float4(colb, bx, by, 0.f);
    }

    grid_barrier(NB);

    // ====== Phase B: stable rank-count sort, one WARP per gaussian ==========
    {
        int wg = blockIdx.x * 8 + wid;       // global warp id
        if (wg < C * N) {
            int cam = wg / N, i = wg - cam * N;
            const float* tz = g_tz + cam * N;
            float ti = tz[i];
            int rank = 0;
            for (int j = lane; j < N; j += 32) {
                float tj = tz[j];
                rank += (tj < ti) || (tj == ti && j < i);   // stable
            }
            #pragma unroll
            for (int d = 16; d > 0; d >>= 1)
                rank += __shfl_xor_sync(0xffffffffu, rank, d);
            if (lane < 3) {
                int src = (cam * N + i) * 3, dst = (cam * N + rank) * 3;
                g_srec4[dst + lane] = g_rec4[src + lane];
            }
        }
    }

    grid_barrier(2 * NB);

    // ================= Phase C: dynamic-queue tiled compositing =============
    // LPT order: heavy center tiles pulled first, light edge tiles pad tail.
    int total = tilesX * tilesY * C * NCHUNK;
    int L = (N + NCHUNK - 1) / NCHUNK;

    if (tid == 0) s_item = atomicAdd(&g_work, 1);
    __syncthreads();

    for (;;) {
        int item = s_item;
        if (item >= total) break;

        int tmp = item;
        int chunk = tmp % NCHUNK; tmp /= NCHUNK;
        int cam   = tmp % C;      tmp /= C;
        int tx    = center_map(tmp % tilesX, tilesX);
        int ty    = center_map(tmp / tilesX, tilesY);

        int gs = chunk * L, ge = min(N, gs + L);
        int x = tx * TILE + (tid & 15);
        int y = ty * TILE + (tid >> 4);
        bool inside = (x < W) && (y < H);
        float pxf = x + 0.5f, pyf = y + 0.5f;
        float tx0 = tx * TILE + 0.5f, tx1 = tx0 + (TILE - 1);
        float ty0 = ty * TILE + 0.5f, ty1 = ty0 + (TILE - 1);

        float T = inside ? 1.0f : 0.0f;
        float aR = 0.f, aG = 0.f, aB = 0.f;
        int base = cam * N;

        for (int b0 = gs; b0 < ge; b0 += 256) {
            int gi = b0 + tid;
            bool keep = false;
            float4 f0, f2;
            if (gi < ge) {
                f0 = g_srec4[(base + gi) * 3];
                f2 = g_srec4[(base + gi) * 3 + 2];
                keep = (f0.x - f2.y <= tx1) && (f0.x + f2.y >= tx0) &&
                       (f0.y - f2.z <= ty1) && (f0.y + f2.z >= ty0);
            }
            unsigned m = __ballot_sync(0xffffffffu, keep);
            if (lane == 0) s_off[wid] = __popc(m);
            __syncthreads();                 // also guards sA reuse vs prev batch
            int pre = 0, cnt = 0;
            #pragma unroll
            for (int w = 0; w < 8; w++) {    // redundant scan: broadcast LDS
                int c = s_off[w];
                pre += (w < wid) ? c : 0;
                cnt += c;
            }
            if (keep) {
                float4 f1 = g_srec4[(base + gi) * 3 + 1];
                int pos = pre + __popc(m & ((1u << lane) - 1));
                sA[pos] = f0; sB[pos] = f1;
                sCb[pos] = f2.x;
            }
            __syncthreads();

            // branchless front-to-back compositing (alpha in log2 domain)
            #pragma unroll 2
            for (int k = 0; k < cnt; k++) {
                float4 a = sA[k], b = sB[k];
                float cb2 = sCb[k];
                float dx = pxf - a.x, dy = pyf - a.y;
                float t1 = fmaf(a.w, dy, a.z * dx);       // A dx + B dy
                float t2 = fmaf(b.x * dy, dy, b.y);       // C dy^2 + lop
                float e2 = fmaf(dx, t1, t2);
                float al = ex2(e2);                       // al <= op <= MAXA
                float w  = al * T;
                aR += w * b.z; aG += w * b.w; aB += w * cb2;
                T -= w;
            }
        }

        int pix = (cam * H + y) * W + x;
        if (inside)
            g_seg[chunk * MAXPIX + pix] = make_float4(aR, aG, aB, T);

        // ---- ticket (release/acquire) + next-item pull, one sync for both --
        int tix = (cam * tilesY + ty) * tilesX + tx;
        if (tid == 0) {
            s_last = (atom_add_acqrel(&g_ctr[tix], 1) == NCHUNK - 1);
            s_item = atomicAdd(&g_work, 1);
        }
        __syncthreads();

        if (s_last) {
            if (inside) {
                float Tc = 1.f, r = 0.f, g = 0.f, b = 0.f;
                #pragma unroll
                for (int s = 0; s < NCHUNK; s++) {
                    float4 v = g_seg[s * MAXPIX + pix];
                    r += Tc * v.x; g += Tc * v.y; b += Tc * v.z;
                    Tc *= v.w;
                }
                out[pix*3] = r; out[pix*3+1] = g; out[pix*3+2] = b;
            }
            if (tid == 0) g_ctr[tix] = 0;     // reset ticket for next replay
            __syncthreads();
        }
    }

    // ---- exit ticket: last block to drain the queue resets global state ----
    __syncthreads();
    if (tid == 0) {
        __threadfence();
        if (atomicAdd(&g_bar, 1) == 3 * NB - 1) {
            g_bar  = 0;
            g_work = 0;
            __threadfence();
        }
    }
}

// ---------------------------------------------------------------------------
extern "C" void kernel_launch(void* const* d_in, const int* in_sizes, int n_in,
                              void* d_out, int out_size) {
    const float* vms   = (const float*)d_in[0];  // (C,4,4)
    const float* Ks    = (const float*)d_in[1];  // (C,3,3)
    const float* means = (const float*)d_in[2];  // (N,3)
    const float* quats = (const float*)d_in[3];  // (N,4)
    const float* lsc   = (const float*)d_in[4];  // (N,3)
    const float* olog  = (const float*)d_in[5];  // (N,)
    const float* clog  = (const float*)d_in[6];  // (N,3)

    int C = in_sizes[0] / 16;
    int N = in_sizes[2] / 3;
    int HW = out_size / (3 * C);
    int W = (int)(sqrt((double)HW) + 0.5);
    int H = HW / W;
    int tilesX = (W + TILE - 1) / TILE;
    int tilesY = (H + TILE - 1) / TILE;

    k_fused<<<NB, 256>>>(vms, Ks, means, quats, lsc, olog, clog,
                         (float*)d_out, C, N, W, H, tilesX, tilesY);
}